// round 14
// baseline (speedup 1.0000x reference)
#include <cuda_runtime.h>
#include <stdint.h>

#define NUM_GRAPHS 4096
#define EMB_DIM    128
#define THREADS    128
#define DEPTH_P    3                 // cp.async ring depth in PAIRS (6 rows)
#define NBLOCKS    (152 * 16)        // GB300: one exact wave at 16 blocks/SM
#define NWARPS     (NBLOCKS * 4)

// zero-initialized at module load; finalize_kernel restores zeros after use,
// so the invariant holds at the start of every kernel_launch call.
__device__ float g_acc[NUM_GRAPHS * EMB_DIM];
__device__ float g_l[NUM_GRAPHS];
__device__ float g_cnt[NUM_GRAPHS];

__device__ __forceinline__ int gid_at(const int* b32, const long long* b64,
                                      bool is64, int i)
{
    return is64 ? (int)b64[i] : b32[i];
}

// first index in (lo, hi) with gid > gseg (batch sorted ascending)
__device__ __forceinline__ int upper_bound_gid(const int* b32, const long long* b64,
                                               bool is64, int lo, int hi, int gseg)
{
    while (lo < hi) {
        int mid = (lo + hi) >> 1;
        if (gid_at(b32, b64, is64, mid) <= gseg) lo = mid + 1; else hi = mid;
    }
    return lo;
}

__global__ __launch_bounds__(THREADS)
void att_partial_kernel(const float* __restrict__ x,
                        const void* __restrict__ batch_raw,
                        const float* __restrict__ w,
                        int n_nodes)
{
    const int t    = threadIdx.x;
    const int warp = t >> 5;
    const int lane = t & 31;

    __shared__ float4 buf[4][DEPTH_P * 2][32];   // 12 KB ring: [warp][row slot][lane]

    // dtype probe: int32 -> word n-1 is the last graph id (!=0);
    // int64 (values < 2^31, LE) -> word n-1 is an upper half (==0).
    const int*       b32 = (const int*)batch_raw;
    const long long* b64 = (const long long*)batch_raw;
    const bool is64 = (b32[n_nodes - 1] == 0);

    const float4 wvec = ((const float4*)w)[lane];

    // perfectly balanced contiguous warp slice
    const int gw       = blockIdx.x * 4 + warp;
    const int per_warp = (n_nodes + NWARPS - 1) / NWARPS;
    const int ws       = gw * per_warp;
    const int we       = min(n_nodes, ws + per_warp);
    if (ws >= we) return;

    const int nrows = we - ws;
    const uint32_t sbase = (uint32_t)__cvta_generic_to_shared(&buf[warp][0][lane]);
    const float* base = x + (size_t)ws * EMB_DIM + lane * 4;

    // ---- single prologue: continuous ring over the WHOLE slice ----
    #pragma unroll
    for (int d = 0; d < DEPTH_P; d++) {
        const int r0 = 2 * d, r1 = 2 * d + 1;
        if (r0 < nrows) {
            const float* src = base + (size_t)r0 * EMB_DIM;
            asm volatile("cp.async.cg.shared.global [%0], [%1], 16;\n"
                         :: "r"(sbase + r0 * 512), "l"(src));
        }
        if (r1 < nrows) {
            const float* src = base + (size_t)r1 * EMB_DIM;
            asm volatile("cp.async.cg.shared.global [%0], [%1], 16;\n"
                         :: "r"(sbase + r1 * 512), "l"(src));
        }
        asm volatile("cp.async.commit_group;\n");
    }

    // segment state (consume-side only; warp-uniform)
    int gseg = gid_at(b32, b64, is64, ws);
    const int glast = gid_at(b32, b64, is64, we - 1);
    int bnd = (gseg == glast) ? we
            : upper_bound_gid(b32, b64, is64, ws + 1, we, gseg);

    float4 acc = make_float4(0.f, 0.f, 0.f, 0.f);
    float  l   = 0.f;
    float  cnt = 0.f;

#define FLUSH() do {                                                        \
        float* dst = g_acc + (size_t)gseg * EMB_DIM + lane * 4;            \
        atomicAdd(dst + 0, acc.x);                                         \
        atomicAdd(dst + 1, acc.y);                                         \
        atomicAdd(dst + 2, acc.z);                                         \
        atomicAdd(dst + 3, acc.w);                                         \
        if (lane == 0) {                                                   \
            atomicAdd(&g_l[gseg],   l);                                    \
            atomicAdd(&g_cnt[gseg], cnt);                                  \
        }                                                                  \
        acc = make_float4(0.f, 0.f, 0.f, 0.f); l = 0.f; cnt = 0.f;         \
    } while (0)

#define BOUNDARY(r) do {                                                   \
        if ((r) == bnd) {      /* warp-uniform, almost never taken */      \
            FLUSH();                                                       \
            gseg = gid_at(b32, b64, is64, (r));                            \
            bnd = (gseg == glast) ? we                                     \
                : upper_bound_gid(b32, b64, is64, (r) + 1, we, gseg);      \
        }                                                                  \
    } while (0)

    int slot = 0;   // row slot of current pair (0, 2 or 4)
    const int npairs = nrows >> 1;

    for (int ip = 0; ip < npairs; ip++) {
        asm volatile("cp.async.wait_group %0;\n" :: "n"(DEPTH_P - 1));
        const float4 xv0 = buf[warp][slot][lane];
        const float4 xv1 = buf[warp][slot + 1][lane];

        // refill this pair's slots with rows 2*ip + 2*DEPTH_P (+1)
        const int nr0 = 2 * ip + 2 * DEPTH_P;
        const int nr1 = nr0 + 1;
        if (nr0 < nrows) {
            const float* src = base + (size_t)nr0 * EMB_DIM;
            asm volatile("cp.async.cg.shared.global [%0], [%1], 16;\n"
                         :: "r"(sbase + slot * 512), "l"(src));
        }
        if (nr1 < nrows) {
            const float* src = base + (size_t)nr1 * EMB_DIM;
            asm volatile("cp.async.cg.shared.global [%0], [%1], 16;\n"
                         :: "r"(sbase + (slot + 1) * 512), "l"(src));
        }
        asm volatile("cp.async.commit_group;\n");

        float p0 = xv0.x*wvec.x + xv0.y*wvec.y + xv0.z*wvec.z + xv0.w*wvec.w;
        float p1 = xv1.x*wvec.x + xv1.y*wvec.y + xv1.z*wvec.z + xv1.w*wvec.w;
        #pragma unroll
        for (int o = 16; o; o >>= 1) {
            p0 += __shfl_xor_sync(0xffffffffu, p0, o);
            p1 += __shfl_xor_sync(0xffffffffu, p1, o);
        }
        // no-max softmax (shift-invariant; scores small enough for fp32 exp)
        const float e0 = __expf(p0);
        const float e1 = __expf(p1);

        const int r = ws + 2 * ip;
        BOUNDARY(r);
        acc.x += e0*xv0.x; acc.y += e0*xv0.y; acc.z += e0*xv0.z; acc.w += e0*xv0.w;
        l += e0; cnt += 1.f;

        BOUNDARY(r + 1);
        acc.x += e1*xv1.x; acc.y += e1*xv1.y; acc.z += e1*xv1.z; acc.w += e1*xv1.w;
        l += e1; cnt += 1.f;

        slot += 2;
        if (slot == 2 * DEPTH_P) slot = 0;
    }

    if (nrows & 1) {
        asm volatile("cp.async.wait_group 0;\n");
        const float4 xv = buf[warp][slot][lane];
        float p = xv.x*wvec.x + xv.y*wvec.y + xv.z*wvec.z + xv.w*wvec.w;
        #pragma unroll
        for (int o = 16; o; o >>= 1) p += __shfl_xor_sync(0xffffffffu, p, o);
        const float e = __expf(p);
        BOUNDARY(we - 1);
        acc.x += e*xv.x; acc.y += e*xv.y; acc.z += e*xv.z; acc.w += e*xv.w;
        l += e; cnt += 1.f;
    }

    FLUSH();   // final segment
    asm volatile("cp.async.wait_group 0;\n");

#undef FLUSH
#undef BOUNDARY
}

// Vectorized finalize: one float4 per thread; a graph = 32 consecutive
// float4 threads = exactly one warp, so g_l/g_cnt read->zero is warp-local.
__global__ __launch_bounds__(512)
void finalize_kernel(const float* __restrict__ w,
                     float* __restrict__ out, int out_size)
{
    const int i = blockIdx.x * 512 + threadIdx.x;   // float4 index, < 131072
    const int g = i >> 5;                           // 32 float4 per graph

    const float4 a = ((const float4*)g_acc)[i];
    const float  l = g_l[g];
    const float  c = g_cnt[g];
    __syncwarp();                                   // warp-local reads done

    const float inv = 1.0f / (fmaxf(l, 1e-30f) * fmaxf(c, 1.0f));
    ((float4*)out)[i] = make_float4(a.x * inv, a.y * inv, a.z * inv, a.w * inv);

    ((float4*)g_acc)[i] = make_float4(0.f, 0.f, 0.f, 0.f);   // self-clean
    if ((i & 31) == 0) { g_l[g] = 0.0f; g_cnt[g] = 0.0f; }

    // second tuple element: att_weight passthrough (32 float4)
    if (blockIdx.x == 0 && threadIdx.x < 32 &&
        out_size >= NUM_GRAPHS * EMB_DIM + EMB_DIM) {
        ((float4*)(out + NUM_GRAPHS * EMB_DIM))[threadIdx.x] =
            ((const float4*)w)[threadIdx.x];
    }
}

extern "C" void kernel_launch(void* const* d_in, const int* in_sizes, int n_in,
                              void* d_out, int out_size)
{
    const float* x     = (const float*)d_in[0];
    const void*  batch = d_in[1];
    const float* w     = (const float*)d_in[2];
    float*       out   = (float*)d_out;
    const int n_nodes  = in_sizes[1];

    att_partial_kernel<<<NBLOCKS, THREADS>>>(x, batch, w, n_nodes);
    finalize_kernel<<<(NUM_GRAPHS * EMB_DIM / 4) / 512, 512>>>(w, out, out_size);
}

// round 15
// speedup vs baseline: 1.0453x; 1.0453x over previous
#include <cuda_runtime.h>
#include <stdint.h>

#define NUM_GRAPHS 4096
#define EMB_DIM    128
#define THREADS    128
#define DEPTH_P    3                 // cp.async ring depth in PAIRS (6 rows)
#define NWAVES     3                 // oversubscribe: wave>=2 gets work-steal
#define NBLOCKS    (152 * 16 * NWAVES)
#define NWARPS     (NBLOCKS * 4)

// zero-initialized at module load; finalize_kernel restores zeros after use,
// so the invariant holds at the start of every kernel_launch call.
__device__ float g_acc[NUM_GRAPHS * EMB_DIM];
__device__ float g_l[NUM_GRAPHS];
__device__ float g_cnt[NUM_GRAPHS];

__device__ __forceinline__ int gid_at(const int* b32, const long long* b64,
                                      bool is64, int i)
{
    return is64 ? (int)b64[i] : b32[i];
}

__global__ __launch_bounds__(THREADS)
void att_partial_kernel(const float* __restrict__ x,
                        const void* __restrict__ batch_raw,
                        const float* __restrict__ w,
                        int n_nodes)
{
    const int t    = threadIdx.x;
    const int warp = t >> 5;
    const int lane = t & 31;

    __shared__ float4 buf[4][DEPTH_P * 2][32];   // 12 KB ring: [warp][row slot][lane]

    // dtype probe: int32 -> word n-1 is the last graph id (!=0);
    // int64 (values < 2^31, LE) -> word n-1 is an upper half (==0).
    const int*       b32 = (const int*)batch_raw;
    const long long* b64 = (const long long*)batch_raw;
    const bool is64 = (b32[n_nodes - 1] == 0);

    const float4 wvec = ((const float4*)w)[lane];

    // balanced contiguous warp slice (small slices; waves>=2 work-steal)
    const int gw       = blockIdx.x * 4 + warp;
    const int per_warp = (n_nodes + NWARPS - 1) / NWARPS;
    const int ws       = gw * per_warp;
    const int we       = min(n_nodes, ws + per_warp);
    if (ws >= we) return;

    const uint32_t sbase = (uint32_t)__cvta_generic_to_shared(&buf[warp][0][lane]);

    int s = ws;
    int gseg = gid_at(b32, b64, is64, ws);
    const int glast = gid_at(b32, b64, is64, we - 1);

    while (s < we) {
        // segment end: we if this is the slice's last graph, else upper_bound
        int e;
        if (gseg == glast) {
            e = we;
        } else {
            int lo = s + 1, hi = we;
            while (lo < hi) {
                int mid = (lo + hi) >> 1;
                if (gid_at(b32, b64, is64, mid) <= gseg) lo = mid + 1; else hi = mid;
            }
            e = lo;
        }
        const int nrows = e - s;

        // ---- cp.async ring (pair-granular groups) over contiguous [s, e) ----
        const float* base = x + (size_t)s * EMB_DIM + lane * 4;

        #pragma unroll
        for (int d = 0; d < DEPTH_P; d++) {
            const int r0 = 2 * d, r1 = 2 * d + 1;
            if (r0 < nrows) {
                const float* src = base + (size_t)r0 * EMB_DIM;
                asm volatile("cp.async.cg.shared.global [%0], [%1], 16;\n"
                             :: "r"(sbase + r0 * 512), "l"(src));
            }
            if (r1 < nrows) {
                const float* src = base + (size_t)r1 * EMB_DIM;
                asm volatile("cp.async.cg.shared.global [%0], [%1], 16;\n"
                             :: "r"(sbase + r1 * 512), "l"(src));
            }
            asm volatile("cp.async.commit_group;\n");
        }

        float4 acc = make_float4(0.f, 0.f, 0.f, 0.f);
        float  l   = 0.f;
        int slot = 0;   // row slot of current pair (0, 2 or 4)

        const int npairs = nrows >> 1;
        for (int ip = 0; ip < npairs; ip++) {
            asm volatile("cp.async.wait_group %0;\n" :: "n"(DEPTH_P - 1));
            const float4 xv0 = buf[warp][slot][lane];
            const float4 xv1 = buf[warp][slot + 1][lane];

            // refill this pair's slots with rows 2*ip + 2*DEPTH_P (+1)
            const int nr0 = 2 * ip + 2 * DEPTH_P;
            const int nr1 = nr0 + 1;
            if (nr0 < nrows) {
                const float* src = base + (size_t)nr0 * EMB_DIM;
                asm volatile("cp.async.cg.shared.global [%0], [%1], 16;\n"
                             :: "r"(sbase + slot * 512), "l"(src));
            }
            if (nr1 < nrows) {
                const float* src = base + (size_t)nr1 * EMB_DIM;
                asm volatile("cp.async.cg.shared.global [%0], [%1], 16;\n"
                             :: "r"(sbase + (slot + 1) * 512), "l"(src));
            }
            asm volatile("cp.async.commit_group;\n");

            float p0 = xv0.x*wvec.x + xv0.y*wvec.y + xv0.z*wvec.z + xv0.w*wvec.w;
            float p1 = xv1.x*wvec.x + xv1.y*wvec.y + xv1.z*wvec.z + xv1.w*wvec.w;
            #pragma unroll
            for (int o = 16; o; o >>= 1) {
                p0 += __shfl_xor_sync(0xffffffffu, p0, o);
                p1 += __shfl_xor_sync(0xffffffffu, p1, o);
            }
            // no-max softmax (shift-invariant; scores small enough for fp32 exp)
            const float e0 = __expf(p0);
            const float e1 = __expf(p1);
            acc.x += e0*xv0.x; acc.y += e0*xv0.y; acc.z += e0*xv0.z; acc.w += e0*xv0.w;
            acc.x += e1*xv1.x; acc.y += e1*xv1.y; acc.z += e1*xv1.z; acc.w += e1*xv1.w;
            l += e0 + e1;

            slot += 2;
            if (slot == 2 * DEPTH_P) slot = 0;
        }
        if (nrows & 1) {
            asm volatile("cp.async.wait_group 0;\n");
            const float4 xv = buf[warp][slot][lane];
            float p = xv.x*wvec.x + xv.y*wvec.y + xv.z*wvec.z + xv.w*wvec.w;
            #pragma unroll
            for (int o = 16; o; o >>= 1) p += __shfl_xor_sync(0xffffffffu, p, o);
            const float e = __expf(p);
            acc.x += e*xv.x; acc.y += e*xv.y; acc.z += e*xv.z; acc.w += e*xv.w;
            l += e;
        }
        asm volatile("cp.async.wait_group 0;\n");   // drain before slot reuse

        // ---- flush segment into global partials ----
        float* dst = g_acc + (size_t)gseg * EMB_DIM + lane * 4;
        atomicAdd(dst + 0, acc.x);
        atomicAdd(dst + 1, acc.y);
        atomicAdd(dst + 2, acc.z);
        atomicAdd(dst + 3, acc.w);
        if (lane == 0) {
            atomicAdd(&g_l[gseg], l);
            atomicAdd(&g_cnt[gseg], (float)nrows);
        }

        s = e;
        if (s < we) gseg = gid_at(b32, b64, is64, s);
    }
}

// Vectorized finalize: one float4 per thread; a graph = 32 consecutive
// float4 threads = exactly one warp, so g_l/g_cnt read->zero is warp-local.
__global__ __launch_bounds__(512)
void finalize_kernel(const float* __restrict__ w,
                     float* __restrict__ out, int out_size)
{
    const int i = blockIdx.x * 512 + threadIdx.x;   // float4 index, < 131072
    const int g = i >> 5;                           // 32 float4 per graph

    const float4 a = ((const float4*)g_acc)[i];
    const float  l = g_l[g];
    const float  c = g_cnt[g];
    __syncwarp();                                   // warp-local reads done

    const float inv = 1.0f / (fmaxf(l, 1e-30f) * fmaxf(c, 1.0f));
    ((float4*)out)[i] = make_float4(a.x * inv, a.y * inv, a.z * inv, a.w * inv);

    ((float4*)g_acc)[i] = make_float4(0.f, 0.f, 0.f, 0.f);   // self-clean
    if ((i & 31) == 0) { g_l[g] = 0.0f; g_cnt[g] = 0.0f; }

    // second tuple element: att_weight passthrough (32 float4)
    if (blockIdx.x == 0 && threadIdx.x < 32 &&
        out_size >= NUM_GRAPHS * EMB_DIM + EMB_DIM) {
        ((float4*)(out + NUM_GRAPHS * EMB_DIM))[threadIdx.x] =
            ((const float4*)w)[threadIdx.x];
    }
}

extern "C" void kernel_launch(void* const* d_in, const int* in_sizes, int n_in,
                              void* d_out, int out_size)
{
    const float* x     = (const float*)d_in[0];
    const void*  batch = d_in[1];
    const float* w     = (const float*)d_in[2];
    float*       out   = (float*)d_out;
    const int n_nodes  = in_sizes[1];

    att_partial_kernel<<<NBLOCKS, THREADS>>>(x, batch, w, n_nodes);
    finalize_kernel<<<(NUM_GRAPHS * EMB_DIM / 4) / 512, 512>>>(w, out, out_size);
}